// round 14
// baseline (speedup 1.0000x reference)
#include <cuda_runtime.h>
#include <math.h>
#include <stdint.h>

#define NSCALE 2
#define NPTS   240000
#define NVOX   80000
#define NPB    120000
#define MPB    30000
#define HDIM   64
#define CDIM   20
#define MIDD   16
#define HIDD   128
#define NIMG   60000
#define NLOSS  5           // vox0, vox1, fuse0, fuse1, final
#define NB     16384       // 14-bit err quantization bins
#define QL     16383.0f
#define NCHUNK 16          // NB / 1024

// ------------------------- static device scratch -------------------------
__device__ float g_H1[NSCALE][(size_t)NVOX * HIDD];
__device__ float g_pred3d[NSCALE][(size_t)NVOX * CDIM];
__device__ int   g_counts[NSCALE][(size_t)NVOX * CDIM];
__device__ int   g_voxlab[NSCALE][NVOX];
__device__ int   g_idx[NSCALE][NIMG];
__device__ float g_P[NSCALE][(size_t)NIMG * HDIM];
__device__ float g_attw[NSCALE][(size_t)NIMG * 2];
__device__ float g_y1[NSCALE][(size_t)NIMG * HDIM];
__device__ float g_y2[NSCALE][(size_t)NIMG * HDIM];
__device__ float g_fpred[NSCALE][(size_t)NIMG * CDIM];
__device__ float g_stats[NSCALE][4 * HDIM];
__device__ unsigned long long g_hist[NLOSS][(size_t)CDIM * NB];
__device__ unsigned long long g_part[NLOSS][CDIM * NCHUNK];
__device__ double g_classLoss[NLOSS][CDIM];
__device__ int    g_gts_vox[NSCALE][CDIM];
__device__ float g_HF[(size_t)NIMG * HIDD];
__device__ float g_fpredF[(size_t)NIMG * CDIM];
__device__ float g_feats[(size_t)NIMG * 2 * HDIM];
__device__ int    g_gts_img[CDIM];
__device__ double g_loss;

// ------------------------- reduction helper -------------------------
__device__ __forceinline__ double blockReduceSumD(double v) {
    __shared__ double sh[32];
    int lane = threadIdx.x & 31, wid = threadIdx.x >> 5;
#pragma unroll
    for (int o = 16; o > 0; o >>= 1) v += __shfl_down_sync(0xffffffffu, v, o);
    if (lane == 0) sh[wid] = v;
    __syncthreads();
    int nw = (blockDim.x + 31) >> 5;
    v = (threadIdx.x < nw) ? sh[threadIdx.x] : 0.0;
    if (wid == 0) {
#pragma unroll
        for (int o = 16; o > 0; o >>= 1) v += __shfl_down_sync(0xffffffffu, v, o);
    }
    return v;
}

// ------------------------- batched elementwise kernels -------------------------
__global__ void k_scatter(const int* __restrict__ coors, const int* __restrict__ labels,
                          int* __restrict__ counts) {
    int s = blockIdx.y;
    int i = blockIdx.x * blockDim.x + threadIdx.x;
    if (i < NPTS)
        atomicAdd(&counts[(size_t)s * NVOX * CDIM +
                          (size_t)coors[(size_t)s * NPTS + i] * CDIM + labels[i]], 1);
}

__global__ void k_argmax(const int* __restrict__ counts, int* __restrict__ voxlab,
                         int* __restrict__ gts) {
    int s = blockIdx.y;
    __shared__ int h[CDIM];
    if (threadIdx.x < CDIM) h[threadIdx.x] = 0;
    __syncthreads();
    int v = blockIdx.x * blockDim.x + threadIdx.x;
    if (v < NVOX) {
        const int* row = counts + (size_t)s * NVOX * CDIM + (size_t)v * CDIM;
        int best = row[0], bi = 0;
#pragma unroll
        for (int c = 1; c < CDIM; c++) { int x = row[c]; if (x > best) { best = x; bi = c; } }
        voxlab[(size_t)s * NVOX + v] = bi;
        atomicAdd(&h[bi], 1);
    }
    __syncthreads();
    if (threadIdx.x < CDIM && h[threadIdx.x]) atomicAdd(&gts[s * CDIM + threadIdx.x], h[threadIdx.x]);
}

__global__ void k_hist(const int* __restrict__ lab, int n, int* __restrict__ gts) {
    __shared__ int h[CDIM];
    if (threadIdx.x < CDIM) h[threadIdx.x] = 0;
    __syncthreads();
    int i = blockIdx.x * blockDim.x + threadIdx.x;
    if (i < n) atomicAdd(&h[lab[i]], 1);
    __syncthreads();
    if (threadIdx.x < CDIM && h[threadIdx.x]) atomicAdd(&gts[threadIdx.x], h[threadIdx.x]);
}

__global__ void k_idxgather(const float4* __restrict__ pts4, const int* __restrict__ coors,
                            const int* __restrict__ p2img, int* __restrict__ idxArr,
                            float4* __restrict__ P4) {
    int s = blockIdx.y;
    int t = blockIdx.x * blockDim.x + threadIdx.x;
    if (t < NIMG * 16) {
        int r = t >> 4, q = t & 15;
        int b = r / MPB;
        int vi = coors[(size_t)s * NPTS + b * NPB + p2img[r]];
        if (q == 0) idxArr[(size_t)s * NIMG + r] = vi;
        P4[(size_t)s * NIMG * 16 + t] = pts4[(size_t)s * NVOX * 16 + (size_t)vi * 16 + q];
    }
}

__global__ void __launch_bounds__(256) k_attfused(
        const float* __restrict__ Pb, const float* __restrict__ imgb,
        float* __restrict__ attwb,
        const float* __restrict__ fc1w, const float* __restrict__ fc1b,
        const float* __restrict__ fc2w, const float* __restrict__ fc2b,
        const float* __restrict__ fc3w, const float* __restrict__ fc3b) {
    int s = blockIdx.y;
    __shared__ float w1[HDIM * MIDD], w2[HDIM * MIDD], w3[2 * MIDD * 2];
    __shared__ float b1[MIDD], b2[MIDD], b3[2];
    int tid = threadIdx.x;
    for (int i = tid; i < HDIM * MIDD; i += 256) {
        w1[i] = fc1w[(size_t)s * HDIM * MIDD + i];
        w2[i] = fc2w[(size_t)s * HDIM * MIDD + i];
    }
    if (tid < 2 * MIDD * 2) w3[tid] = fc3w[s * 2 * MIDD * 2 + tid];
    if (tid < MIDD) { b1[tid] = fc1b[s * MIDD + tid]; b2[tid] = fc2b[s * MIDD + tid]; }
    if (tid < 2) b3[tid] = fc3b[s * 2 + tid];
    __syncthreads();
    int r = blockIdx.x * blockDim.x + tid;
    if (r >= NIMG) return;
    float h1[MIDD], h2[MIDD];
#pragma unroll
    for (int j = 0; j < MIDD; j++) { h1[j] = b1[j]; h2[j] = b2[j]; }
    const float4* p4 = (const float4*)(Pb + (size_t)s * NIMG * HDIM + (size_t)r * HDIM);
    const float4* v4 = (const float4*)(imgb + (size_t)s * NIMG * HDIM + (size_t)r * HDIM);
#pragma unroll 4
    for (int k4 = 0; k4 < 16; k4++) {
        float4 a = p4[k4], b = v4[k4];
        const float* wa = &w1[(4 * k4) * MIDD];
        const float* wb = &w2[(4 * k4) * MIDD];
#pragma unroll
        for (int j = 0; j < MIDD; j++) {
            h1[j] += a.x * wa[j] + a.y * wa[MIDD + j] + a.z * wa[2 * MIDD + j] + a.w * wa[3 * MIDD + j];
            h2[j] += b.x * wb[j] + b.y * wb[MIDD + j] + b.z * wb[2 * MIDD + j] + b.w * wb[3 * MIDD + j];
        }
    }
    float z0 = b3[0], z1 = b3[1];
#pragma unroll
    for (int j = 0; j < MIDD; j++) {
        z0 += h1[j] * w3[j * 2 + 0] + h2[j] * w3[(MIDD + j) * 2 + 0];
        z1 += h1[j] * w3[j * 2 + 1] + h2[j] * w3[(MIDD + j) * 2 + 1];
    }
    attwb[(size_t)s * NIMG * 2 + 2 * r + 0] = 1.f / (1.f + expf(-z0));
    attwb[(size_t)s * NIMG * 2 + 2 * r + 1] = 1.f / (1.f + expf(-z1));
}

#define ROWSPB 512
__global__ void k_colstats(const float* __restrict__ y1b, const float* __restrict__ y2b,
                           float* __restrict__ statsb) {
    int s = blockIdx.y >> 1, sel = blockIdx.y & 1;
    const float* y = (sel ? y2b : y1b) + (size_t)s * NIMG * HDIM;
    float* stats = statsb + s * 4 * HDIM + sel * 2 * HDIM;
    const int col = threadIdx.x & 63;
    const int grp = threadIdx.x >> 6;
    float sv = 0.f, q = 0.f;
    int r0 = blockIdx.x * ROWSPB;
    int rend = r0 + ROWSPB; if (rend > NIMG) rend = NIMG;
    for (int r = r0 + grp; r < rend; r += 4) {
        float v = y[(size_t)r * HDIM + col];
        sv += v; q += v * v;
    }
    __shared__ float sh[2][4][64];
    sh[0][grp][col] = sv; sh[1][grp][col] = q;
    __syncthreads();
    if (grp == 0) {
        sv = sh[0][0][col] + sh[0][1][col] + sh[0][2][col] + sh[0][3][col];
        q = sh[1][0][col] + sh[1][1][col] + sh[1][2][col] + sh[1][3][col];
        atomicAdd(&stats[col], sv);
        atomicAdd(&stats[64 + col], q);
    }
}

__global__ void k_fuse(const float* __restrict__ y1b, const float* __restrict__ y2b,
                       const float* __restrict__ attwb, const float* __restrict__ statsb,
                       const float* __restrict__ g1, const float* __restrict__ b1,
                       const float* __restrict__ g2, const float* __restrict__ b2) {
    int s = blockIdx.y;
    int t = blockIdx.x * blockDim.x + threadIdx.x;
    if (t >= NIMG * HDIM) return;
    int r = t >> 6, c = t & 63;
    const float* stats = statsb + s * 4 * HDIM;
    const float n = (float)NIMG;
    float mu1 = stats[c] / n;        float var1 = stats[64 + c] / n - mu1 * mu1;
    float mu2 = stats[128 + c] / n;  float var2 = stats[192 + c] / n - mu2 * mu2;
    float v1 = fmaxf((y1b[(size_t)s * NIMG * HDIM + t] - mu1) * rsqrtf(var1 + 1e-5f) * g1[s * HDIM + c] + b1[s * HDIM + c], 0.f);
    float v2 = fmaxf((y2b[(size_t)s * NIMG * HDIM + t] - mu2) * rsqrtf(var2 + 1e-5f) * g2[s * HDIM + c] + b2[s * HDIM + c], 0.f);
    g_feats[(size_t)r * (2 * HDIM) + s * HDIM + c] =
        v1 * attwb[(size_t)s * NIMG * 2 + 2 * r] + v2 * attwb[(size_t)s * NIMG * 2 + 2 * r + 1];
}

// ------------------------- big GEMM (f32x2, A stored duplicated) -------------------------
template <int BM, int BN, int TM, int TN, bool RELU>
__global__ void __launch_bounds__(256) k_gemm2(const float* __restrict__ A0, int lda, size_t sA,
                                               const float* __restrict__ W0, size_t sW,
                                               const float* __restrict__ bias0, size_t sB,
                                               float* __restrict__ C0, size_t sC,
                                               int M, int N, int K) {
    constexpr int TX = BN / TN;
    constexpr int TY = BM / TM;
    static_assert(TX * TY == 256 && TM == 8 && (TN == 4 || TN == 8), "bad tile");
    const float* A = A0 + (size_t)blockIdx.z * sA;
    const float* W = W0 + (size_t)blockIdx.z * sW;
    const float* bias = bias0 + (size_t)blockIdx.z * sB;
    float* Cm = C0 + (size_t)blockIdx.z * sC;
    __shared__ __align__(16) float As2[16][2 * BM + 8];   // duplicated pairs
    __shared__ __align__(16) float Ws[16][BN + 4];
    const int bm = blockIdx.y * BM, bn = blockIdx.x * BN;
    const int tid = threadIdx.x;
    const int tx = tid % TX, ty = tid / TX;
    unsigned long long acc[TM][TN / 2] = {};
    for (int k0 = 0; k0 < K; k0 += 16) {
#pragma unroll
        for (int it = 0; it < BM / 64; it++) {
            int g = tid + it * 256;
            int m = g >> 2, q = g & 3;
            int gm = bm + m;
            float4 v = make_float4(0.f, 0.f, 0.f, 0.f);
            if (gm < M) v = *(const float4*)&A[(size_t)gm * lda + k0 + 4 * q];
            As2[4 * q + 0][2 * m] = v.x; As2[4 * q + 0][2 * m + 1] = v.x;
            As2[4 * q + 1][2 * m] = v.y; As2[4 * q + 1][2 * m + 1] = v.y;
            As2[4 * q + 2][2 * m] = v.z; As2[4 * q + 2][2 * m + 1] = v.z;
            As2[4 * q + 3][2 * m] = v.w; As2[4 * q + 3][2 * m + 1] = v.w;
        }
#pragma unroll
        for (int it = 0; it < BN / 64; it++) {
            int g = tid + it * 256;
            int kk = g / (BN / 4), nq = g % (BN / 4);
            *(float4*)&Ws[kk][4 * nq] = *(const float4*)&W[(size_t)(k0 + kk) * N + bn + 4 * nq];
        }
        __syncthreads();
#pragma unroll
        for (int kk = 0; kk < 16; kk++) {
            unsigned long long a2[TM];
#pragma unroll
            for (int p = 0; p < TM / 2; p++)
                *(ulonglong2*)&a2[2 * p] = *(const ulonglong2*)&As2[kk][2 * (ty * TM) + 4 * p];
            unsigned long long b2[TN / 2];
            *(ulonglong2*)&b2[0] = *(const ulonglong2*)&Ws[kk][tx * TN];
            if constexpr (TN == 8) {
                *(ulonglong2*)&b2[2] = *(const ulonglong2*)&Ws[kk][tx * TN + 4];
            }
#pragma unroll
            for (int i = 0; i < TM; i++) {
#pragma unroll
                for (int j = 0; j < TN / 2; j++)
                    asm("fma.rn.f32x2 %0, %1, %2, %0;" : "+l"(acc[i][j]) : "l"(a2[i]), "l"(b2[j]));
            }
        }
        __syncthreads();
    }
#pragma unroll
    for (int i = 0; i < TM; i++) {
        int gm = bm + ty * TM + i;
        if (gm >= M) continue;
#pragma unroll
        for (int j = 0; j < TN / 2; j++) {
            int gn = bn + tx * TN + 2 * j;
            float lo = __uint_as_float((unsigned)(acc[i][j] & 0xFFFFFFFFull)) + bias[gn];
            float hi = __uint_as_float((unsigned)(acc[i][j] >> 32)) + bias[gn + 1];
            if (RELU) { lo = fmaxf(lo, 0.f); hi = fmaxf(hi, 0.f); }
            *(float2*)&Cm[(size_t)gm * N + gn] = make_float2(lo, hi);
        }
    }
}

// ------------------------- small-N GEMM (f32x2, N padded to 32, A duplicated) -------------------------
template <bool RELU>
__global__ void __launch_bounds__(256) k_gemmS(const float* __restrict__ A0, int lda, size_t sA,
                                               const float* __restrict__ W0, size_t sW,
                                               const float* __restrict__ bias0, size_t sB,
                                               float* __restrict__ C0, size_t sC,
                                               int M, int N, int K) {
    constexpr int BM = 256, BN = 32, TM = 8, TN = 4;
    constexpr int TX = BN / TN;   // 8
    const float* A = A0 + (size_t)blockIdx.z * sA;
    const float* W = W0 + (size_t)blockIdx.z * sW;
    const float* bias = bias0 + (size_t)blockIdx.z * sB;
    float* Cm = C0 + (size_t)blockIdx.z * sC;
    __shared__ __align__(16) float As2[16][2 * BM + 8];
    __shared__ __align__(16) float Ws[16][BN + 4];
    const int bm = blockIdx.y * BM;
    const int tid = threadIdx.x;
    const int tx = tid % TX, ty = tid / TX;   // ty in 0..31
    unsigned long long acc[TM][TN / 2] = {};
    for (int k0 = 0; k0 < K; k0 += 16) {
#pragma unroll
        for (int it = 0; it < BM / 64; it++) {
            int g = tid + it * 256;
            int m = g >> 2, q = g & 3;
            int gm = bm + m;
            float4 v = make_float4(0.f, 0.f, 0.f, 0.f);
            if (gm < M) v = *(const float4*)&A[(size_t)gm * lda + k0 + 4 * q];
            As2[4 * q + 0][2 * m] = v.x; As2[4 * q + 0][2 * m + 1] = v.x;
            As2[4 * q + 1][2 * m] = v.y; As2[4 * q + 1][2 * m + 1] = v.y;
            As2[4 * q + 2][2 * m] = v.z; As2[4 * q + 2][2 * m + 1] = v.z;
            As2[4 * q + 3][2 * m] = v.w; As2[4 * q + 3][2 * m + 1] = v.w;
        }
#pragma unroll
        for (int e = tid; e < 16 * BN; e += 256) {
            int kk = e >> 5, n2 = e & 31;
            Ws[kk][n2] = (n2 < N) ? W[(size_t)(k0 + kk) * N + n2] : 0.f;
        }
        __syncthreads();
#pragma unroll
        for (int kk = 0; kk < 16; kk++) {
            unsigned long long a2[TM];
#pragma unroll
            for (int p = 0; p < TM / 2; p++)
                *(ulonglong2*)&a2[2 * p] = *(const ulonglong2*)&As2[kk][2 * (ty * TM) + 4 * p];
            unsigned long long b2[TN / 2];
            *(ulonglong2*)&b2[0] = *(const ulonglong2*)&Ws[kk][tx * TN];
#pragma unroll
            for (int i = 0; i < TM; i++) {
#pragma unroll
                for (int j = 0; j < TN / 2; j++)
                    asm("fma.rn.f32x2 %0, %1, %2, %0;" : "+l"(acc[i][j]) : "l"(a2[i]), "l"(b2[j]));
            }
        }
        __syncthreads();
    }
#pragma unroll
    for (int i = 0; i < TM; i++) {
        int gm = bm + ty * TM + i;
        if (gm >= M) continue;
#pragma unroll
        for (int j = 0; j < TN / 2; j++) {
            int gn = tx * TN + 2 * j;
            if (gn + 1 < N) {
                float lo = __uint_as_float((unsigned)(acc[i][j] & 0xFFFFFFFFull)) + bias[gn];
                float hi = __uint_as_float((unsigned)(acc[i][j] >> 32)) + bias[gn + 1];
                if (RELU) { lo = fmaxf(lo, 0.f); hi = fmaxf(hi, 0.f); }
                *(float2*)&Cm[(size_t)gm * N + gn] = make_float2(lo, hi);
            } else if (gn < N) {
                float lo = __uint_as_float((unsigned)(acc[i][j] & 0xFFFFFFFFull)) + bias[gn];
                if (RELU) lo = fmaxf(lo, 0.f);
                Cm[(size_t)gm * N + gn] = lo;
            }
        }
    }
}

// ------------------------- loss kernels -------------------------
__global__ void k_softmax_hist(const float* __restrict__ logits0, size_t sL,
                               const int* __restrict__ lab0, int sLab,
                               int n, float ce_w, unsigned long long* __restrict__ hist0) {
    int s = blockIdx.y;
    const float* logits = logits0 + (size_t)s * sL;
    const int* lab = lab0 + (size_t)s * sLab;
    unsigned long long* hist = hist0 + (size_t)s * CDIM * NB;
    int i = blockIdx.x * blockDim.x + threadIdx.x;
    double ce = 0.0;
    if (i < n) {
        float z[CDIM];
        const float4* zr = (const float4*)(logits + (size_t)i * CDIM);
#pragma unroll
        for (int q4 = 0; q4 < 5; q4++) {
            float4 v = zr[q4];
            z[4 * q4 + 0] = v.x; z[4 * q4 + 1] = v.y;
            z[4 * q4 + 2] = v.z; z[4 * q4 + 3] = v.w;
        }
        float m = z[0];
#pragma unroll
        for (int c = 1; c < CDIM; c++) m = fmaxf(m, z[c]);
        float se = 0.f;
#pragma unroll
        for (int c = 0; c < CDIM; c++) se += expf(z[c] - m);
        float ls = logf(se);
        int l = lab[i];
        ce = -(double)(z[l] - m - ls);
#pragma unroll
        for (int c = 0; c < CDIM; c++) {
            float p = expf(z[c] - m - ls);
            unsigned long long fg = (c == l) ? 1ull : 0ull;
            float err = fabsf((float)(c == l) - p);
            uint32_t q = (uint32_t)__float2uint_rn(err * QL);
            if (q > (NB - 1)) q = NB - 1;
            atomicAdd(&hist[(size_t)c * NB + q], (1ull << 32) | fg);
        }
    }
    double tot = blockReduceSumD(ce);
    if (threadIdx.x == 0) atomicAdd(&g_loss, tot * (double)ce_w / (double)n);
}

__global__ void k_lovpart(const unsigned long long* __restrict__ hist0,
                          unsigned long long* __restrict__ part0) {
    int inst = blockIdx.x / (CDIM * NCHUNK);
    int rem = blockIdx.x % (CDIM * NCHUNK);
    int c = rem / NCHUNK, chunk = rem % NCHUNK;
    const unsigned long long* h = hist0 + (size_t)inst * CDIM * NB + (size_t)c * NB + chunk * 1024;
    int t = threadIdx.x;
    unsigned long long s = 0;
#pragma unroll
    for (int i = 0; i < 4; i++) s += h[t * 4 + i];
    __shared__ unsigned long long sh[8];
#pragma unroll
    for (int o = 16; o > 0; o >>= 1) s += __shfl_down_sync(0xffffffffu, s, o);
    if ((t & 31) == 0) sh[t >> 5] = s;
    __syncthreads();
    if (t == 0) {
        unsigned long long v = 0;
#pragma unroll
        for (int w = 0; w < 8; w++) v += sh[w];
        part0[inst * CDIM * NCHUNK + rem] = v;
    }
}

__global__ void k_loveval(const unsigned long long* __restrict__ hist0,
                          const unsigned long long* __restrict__ part0,
                          const int* __restrict__ gts0, int sGts,
                          double* __restrict__ cls0) {
    int inst = blockIdx.x / (CDIM * NCHUNK);
    int rem = blockIdx.x % (CDIM * NCHUNK);
    int c = rem / NCHUNK, chunk = rem % NCHUNK;
    const int* gts = gts0 + inst * sGts;
    int gi = gts[c];
    if (gi == 0) return;
    float g = (float)gi;
    int t = threadIdx.x;
    __shared__ unsigned long long shOff;
    __shared__ unsigned long long shWarp[8];
    __shared__ double shD[8];
    const unsigned long long* part = part0 + inst * CDIM * NCHUNK;
    if (t == 0) {
        unsigned long long o = 0;
        for (int k = chunk + 1; k < NCHUNK; k++) o += part[c * NCHUNK + k];
        shOff = o;
    }
    const unsigned long long* h = hist0 + (size_t)inst * CDIM * NB + (size_t)c * NB + chunk * 1024;
    unsigned long long v[4]; unsigned long long tot = 0;
#pragma unroll
    for (int i = 0; i < 4; i++) { v[i] = h[1023 - (4 * t + i)]; tot += v[i]; }
    unsigned long long incl = tot;
#pragma unroll
    for (int o = 1; o < 32; o <<= 1) {
        unsigned long long u = __shfl_up_sync(0xffffffffu, incl, o);
        if ((t & 31) >= o) incl += u;
    }
    if ((t & 31) == 31) shWarp[t >> 5] = incl;
    __syncthreads();
    unsigned long long warpOff = 0;
    for (int w = 0; w < (t >> 5); w++) warpOff += shWarp[w];
    unsigned long long excl = shOff + warpOff + (incl - tot);
    unsigned long long P = excl >> 32, F = excl & 0xFFFFFFFFull;
    double acc = 0.0;
#pragma unroll
    for (int i = 0; i < 4; i++) {
        unsigned long long nb = v[i] >> 32, fb = v[i] & 0xFFFFFFFFull;
        if (nb) {
            int bin = chunk * 1024 + 1023 - (4 * t + i);
            float e = (float)bin * (1.0f / QL);
            float Pf = (float)P, Ff = (float)F;
            float Js = 1.f - (g - Ff) / (g + Pf - Ff);
            float Pe = (float)(P + nb), Fe = (float)(F + fb);
            float Je = 1.f - (g - Fe) / (g + Pe - Fe);
            acc += (double)(e * (Je - Js));
            P += nb; F += fb;
        }
    }
#pragma unroll
    for (int o = 16; o > 0; o >>= 1) acc += __shfl_down_sync(0xffffffffu, acc, o);
    if ((t & 31) == 0) shD[t >> 5] = acc;
    __syncthreads();
    if (t == 0) {
        double s = 0.0;
#pragma unroll
        for (int w = 0; w < 8; w++) s += shD[w];
        atomicAdd(&cls0[inst * CDIM + c], s);
    }
}

__global__ void k_lovreduceAll() {
    int tid = threadIdx.x;
    const float w[NLOSS] = {1.f, 1.f, 0.5f, 0.5f, 1.f};
    double total = 0.0;
#pragma unroll
    for (int li = 0; li < NLOSS; li++) {
        const int* gts = (li == 0) ? g_gts_vox[0] : (li == 1) ? g_gts_vox[1] : g_gts_img;
        double v = 0.0; int pc = 0;
        if (tid < CDIM && gts[tid] > 0) { v = g_classLoss[li][tid]; pc = 1; }
#pragma unroll
        for (int o = 16; o > 0; o >>= 1) {
            v += __shfl_down_sync(0xffffffffu, v, o);
            pc += __shfl_down_sync(0xffffffffu, pc, o);
        }
        if (tid == 0) total += (double)w[li] * v / (double)(pc > 0 ? pc : 1);
    }
    if (tid == 0) atomicAdd(&g_loss, total);
}

__global__ void k_kl(double w, const float* __restrict__ fpredb,
                     const float* __restrict__ predb, const int* __restrict__ idxb) {
    int s = blockIdx.y;
    int r = blockIdx.x * blockDim.x + threadIdx.x;
    double local = 0.0;
    if (r < NIMG) {
        float zf[CDIM], zp[CDIM];
        int vi = idxb[(size_t)s * NIMG + r];
        const float4* fr = (const float4*)(fpredb + (size_t)s * NIMG * CDIM + (size_t)r * CDIM);
        const float4* pr = (const float4*)(predb + (size_t)s * NVOX * CDIM + (size_t)vi * CDIM);
#pragma unroll
        for (int q4 = 0; q4 < 5; q4++) {
            float4 a = fr[q4], b = pr[q4];
            zf[4 * q4 + 0] = a.x; zf[4 * q4 + 1] = a.y; zf[4 * q4 + 2] = a.z; zf[4 * q4 + 3] = a.w;
            zp[4 * q4 + 0] = b.x; zp[4 * q4 + 1] = b.y; zp[4 * q4 + 2] = b.z; zp[4 * q4 + 3] = b.w;
        }
        float mf = zf[0], mp = zp[0];
#pragma unroll
        for (int c = 1; c < CDIM; c++) { mf = fmaxf(mf, zf[c]); mp = fmaxf(mp, zp[c]); }
        float sf = 0.f, sp = 0.f;
#pragma unroll
        for (int c = 0; c < CDIM; c++) { sf += expf(zf[c] - mf); sp += expf(zp[c] - mp); }
        float lsf = logf(sf), lsp = logf(sp);
        float acc = 0.f;
#pragma unroll
        for (int c = 0; c < CDIM; c++) {
            float lp = zf[c] - mf - lsf;
            float p = expf(lp);
            float lq = zp[c] - mp - lsp;
            acc += p * (lp - lq);
        }
        local = (double)acc;
    }
    double tot = blockReduceSumD(local);
    if (threadIdx.x == 0) atomicAdd(&g_loss, tot * w);
}

__global__ void k_finish(float* out) { out[0] = (float)g_loss; }

// ------------------------- host -------------------------
static inline int ceildiv(int a, int b) { return (a + b - 1) / b; }

extern "C" void kernel_launch(void* const* d_in, const int* in_sizes, int n_in,
                              void* d_out, int out_size) {
    const float* img_feat = (const float*)d_in[0];
    const float* pts_feat = (const float*)d_in[1];
    const int*   coors_inv = (const int*)d_in[2];
    const int*   labels   = (const int*)d_in[3];
    const int*   img_label = (const int*)d_in[4];
    const int*   p2img    = (const int*)d_in[5];
    const float* w3a = (const float*)d_in[6];  const float* b3a = (const float*)d_in[7];
    const float* w3b = (const float*)d_in[8];  const float* b3b = (const float*)d_in[9];
    const float* wfa = (const float*)d_in[10]; const float* bfa = (const float*)d_in[11];
    const float* wfb = (const float*)d_in[12]; const float* bfb = (const float*)d_in[13];
    const float* fc1w = (const float*)d_in[14]; const float* fc1b = (const float*)d_in[15];
    const float* fc2w = (const float*)d_in[16]; const float* fc2b = (const float*)d_in[17];
    const float* fc3w = (const float*)d_in[18]; const float* fc3b = (const float*)d_in[19];
    const float* c1w = (const float*)d_in[20]; const float* c1b = (const float*)d_in[21];
    const float* bn1g = (const float*)d_in[22]; const float* bn1b = (const float*)d_in[23];
    const float* c2w = (const float*)d_in[24]; const float* c2b = (const float*)d_in[25];
    const float* bn2g = (const float*)d_in[26]; const float* bn2b = (const float*)d_in[27];
    const float* clw1 = (const float*)d_in[28]; const float* clb1 = (const float*)d_in[29];
    const float* clw2 = (const float*)d_in[30]; const float* clb2 = (const float*)d_in[31];

    void *pv;
    cudaGetSymbolAddress(&pv, g_H1);       float* H1b = (float*)pv;
    cudaGetSymbolAddress(&pv, g_pred3d);   float* predb = (float*)pv;
    cudaGetSymbolAddress(&pv, g_counts);   int* countsb = (int*)pv;
    cudaGetSymbolAddress(&pv, g_voxlab);   int* voxlabb = (int*)pv;
    cudaGetSymbolAddress(&pv, g_idx);      int* idxb = (int*)pv;
    cudaGetSymbolAddress(&pv, g_P);        float* Pb = (float*)pv;
    cudaGetSymbolAddress(&pv, g_attw);     float* attwb = (float*)pv;
    cudaGetSymbolAddress(&pv, g_y1);       float* y1b = (float*)pv;
    cudaGetSymbolAddress(&pv, g_y2);       float* y2b = (float*)pv;
    cudaGetSymbolAddress(&pv, g_fpred);    float* fpredb = (float*)pv;
    cudaGetSymbolAddress(&pv, g_stats);    float* statsb = (float*)pv;
    cudaGetSymbolAddress(&pv, g_hist);     unsigned long long* histb = (unsigned long long*)pv;
    cudaGetSymbolAddress(&pv, g_part);     unsigned long long* partb = (unsigned long long*)pv;
    cudaGetSymbolAddress(&pv, g_classLoss);double* clsb = (double*)pv;
    cudaGetSymbolAddress(&pv, g_gts_vox);  int* gtsvoxb = (int*)pv;
    cudaGetSymbolAddress(&pv, g_HF);       float* HF = (float*)pv;
    cudaGetSymbolAddress(&pv, g_fpredF);   float* fpredF = (float*)pv;
    cudaGetSymbolAddress(&pv, g_feats);    float* feats = (float*)pv;
    cudaGetSymbolAddress(&pv, g_gts_img);  int* gtsimg = (int*)pv;
    cudaGetSymbolAddress(&pv, g_loss);     void* p_loss = pv;

    static cudaStream_t sM = nullptr, sL = nullptr;
    static cudaEvent_t evFork = nullptr, evPred = nullptr, evFpred = nullptr;
    static cudaEvent_t evFeats = nullptr, evY2 = nullptr;
    static cudaEvent_t evEndM = nullptr, evEndL = nullptr;
    if (!sM) {
        cudaStreamCreateWithFlags(&sM, cudaStreamNonBlocking);
        cudaStreamCreateWithFlags(&sL, cudaStreamNonBlocking);
        cudaEventCreateWithFlags(&evFork, cudaEventDisableTiming);
        cudaEventCreateWithFlags(&evPred, cudaEventDisableTiming);
        cudaEventCreateWithFlags(&evFpred, cudaEventDisableTiming);
        cudaEventCreateWithFlags(&evFeats, cudaEventDisableTiming);
        cudaEventCreateWithFlags(&evY2, cudaEventDisableTiming);
        cudaEventCreateWithFlags(&evEndM, cudaEventDisableTiming);
        cudaEventCreateWithFlags(&evEndL, cudaEventDisableTiming);
    }

    cudaStream_t st0 = 0;
    cudaMemsetAsync(p_loss, 0, sizeof(double), st0);
    cudaMemsetAsync(gtsimg, 0, CDIM * sizeof(int), st0);
    cudaMemsetAsync(countsb, 0, (size_t)NSCALE * NVOX * CDIM * sizeof(int), st0);
    cudaMemsetAsync(gtsvoxb, 0, NSCALE * CDIM * sizeof(int), st0);
    cudaMemsetAsync(histb, 0, (size_t)NLOSS * CDIM * NB * sizeof(unsigned long long), st0);
    cudaMemsetAsync(clsb, 0, NLOSS * CDIM * sizeof(double), st0);
    cudaMemsetAsync(statsb, 0, NSCALE * 4 * HDIM * sizeof(float), st0);
    k_hist<<<ceildiv(NIMG, 256), 256, 0, st0>>>(img_label, NIMG, gtsimg);
    cudaEventRecord(evFork, st0);
    cudaStreamWaitEvent(sM, evFork, 0);
    cudaStreamWaitEvent(sL, evFork, 0);

    auto hist = [&](int i) { return histb + (size_t)i * CDIM * NB; };
    auto part = [&](int i) { return partb + (size_t)i * CDIM * NCHUNK; };
    auto cls  = [&](int i) { return clsb + (size_t)i * CDIM; };

    // ===== LOSS stream independent prefix (record evY2 before sM waits) =====
    k_gemm2<128, 64, 8, 4, false><<<dim3(1, ceildiv(NIMG, 128), 2), 256, 0, sL>>>(
        img_feat, HDIM, (size_t)NIMG * HDIM, c2w, (size_t)HDIM * HDIM, c2b, HDIM,
        y2b, (size_t)NIMG * HDIM, NIMG, HDIM, HDIM);
    cudaEventRecord(evY2, sL);
    k_scatter<<<dim3(ceildiv(NPTS, 256), 2), 256, 0, sL>>>(coors_inv, labels, countsb);
    k_argmax<<<dim3(ceildiv(NVOX, 256), 2), 256, 0, sL>>>(countsb, voxlabb, gtsvoxb);

    // ================= MAIN stream =================
    k_gemm2<128, 128, 8, 8, true><<<dim3(1, ceildiv(NVOX, 128), 2), 256, 0, sM>>>(
        pts_feat, HDIM, (size_t)NVOX * HDIM, w3a, (size_t)HDIM * HIDD, b3a, HIDD,
        H1b, (size_t)NVOX * HIDD, NVOX, HIDD, HDIM);
    k_gemmS<false><<<dim3(1, ceildiv(NVOX, 256), 2), 256, 0, sM>>>(
        H1b, HIDD, (size_t)NVOX * HIDD, w3b, (size_t)HIDD * CDIM, b3b, CDIM,
        predb, (size_t)NVOX * CDIM, NVOX, CDIM, HIDD);
    cudaEventRecord(evPred, sM);

    k_idxgather<<<dim3(ceildiv(NIMG * 16, 256), 2), 256, 0, sM>>>(
        (const float4*)pts_feat, coors_inv, p2img, idxb, (float4*)Pb);
    k_attfused<<<dim3(ceildiv(NIMG, 256), 2), 256, 0, sM>>>(
        Pb, img_feat, attwb, fc1w, fc1b, fc2w, fc2b, fc3w, fc3b);
    k_gemm2<128, 64, 8, 4, false><<<dim3(1, ceildiv(NIMG, 128), 2), 256, 0, sM>>>(
        Pb, HDIM, (size_t)NIMG * HDIM, c1w, (size_t)HDIM * HDIM, c1b, HDIM,
        y1b, (size_t)NIMG * HDIM, NIMG, HDIM, HDIM);
    cudaStreamWaitEvent(sM, evY2, 0);
    k_colstats<<<dim3(ceildiv(NIMG, ROWSPB), 4), 256, 0, sM>>>(y1b, y2b, statsb);
    k_fuse<<<dim3(ceildiv(NIMG * HDIM, 256), 2), 256, 0, sM>>>(
        y1b, y2b, attwb, statsb, bn1g, bn1b, bn2g, bn2b);
    cudaEventRecord(evFeats, sM);

    k_gemm2<128, 128, 8, 8, true><<<dim3(1, ceildiv(NIMG, 128), 2), 256, 0, sM>>>(
        feats, 2 * HDIM, (size_t)HDIM, wfa, (size_t)HDIM * HIDD, bfa, HIDD,
        H1b, (size_t)NVOX * HIDD, NIMG, HIDD, HDIM);
    k_gemmS<false><<<dim3(1, ceildiv(NIMG, 256), 2), 256, 0, sM>>>(
        H1b, HIDD, (size_t)NVOX * HIDD, wfb, (size_t)HIDD * CDIM, bfb, CDIM,
        fpredb, (size_t)NIMG * CDIM, NIMG, CDIM, HIDD);
    cudaEventRecord(evFpred, sM);
    cudaEventRecord(evEndM, sM);

    // ===== LOSS stream gated suffix =====
    cudaStreamWaitEvent(sL, evPred, 0);
    k_softmax_hist<<<dim3(ceildiv(NVOX, 256), 2), 256, 0, sL>>>(
        predb, (size_t)NVOX * CDIM, voxlabb, NVOX, NVOX, 1.0f, hist(0));
    k_lovpart<<<2 * CDIM * NCHUNK, 256, 0, sL>>>(hist(0), part(0));
    k_loveval<<<2 * CDIM * NCHUNK, 256, 0, sL>>>(hist(0), part(0), gtsvoxb, CDIM, cls(0));

    cudaStreamWaitEvent(sL, evFeats, 0);
    k_gemm2<128, 128, 8, 8, true><<<dim3(1, ceildiv(NIMG, 128), 1), 256, 0, sL>>>(
        feats, 2 * HDIM, 0, clw1, 0, clb1, 0, HF, 0, NIMG, HIDD, 2 * HDIM);
    k_gemmS<false><<<dim3(1, ceildiv(NIMG, 256), 1), 256, 0, sL>>>(
        HF, HIDD, 0, clw2, 0, clb2, 0, fpredF, 0, NIMG, CDIM, HIDD);
    k_softmax_hist<<<dim3(ceildiv(NIMG, 256), 1), 256, 0, sL>>>(
        fpredF, 0, img_label, 0, NIMG, 1.0f, hist(4));
    k_lovpart<<<CDIM * NCHUNK, 256, 0, sL>>>(hist(4), part(4));
    k_loveval<<<CDIM * NCHUNK, 256, 0, sL>>>(hist(4), part(4), gtsimg, 0, cls(4));

    cudaStreamWaitEvent(sL, evFpred, 0);
    k_softmax_hist<<<dim3(ceildiv(NIMG, 256), 2), 256, 0, sL>>>(
        fpredb, (size_t)NIMG * CDIM, img_label, 0, NIMG, 0.5f, hist(2));
    k_lovpart<<<2 * CDIM * NCHUNK, 256, 0, sL>>>(hist(2), part(2));
    k_loveval<<<2 * CDIM * NCHUNK, 256, 0, sL>>>(hist(2), part(2), gtsimg, 0, cls(2));
    k_kl<<<dim3(ceildiv(NIMG, 256), 2), 256, 0, sL>>>(
        0.025 / ((double)NIMG * (double)CDIM), fpredb, predb, idxb);
    k_lovreduceAll<<<1, 32, 0, sL>>>();
    cudaEventRecord(evEndL, sL);

    cudaStreamWaitEvent(st0, evEndM, 0);
    cudaStreamWaitEvent(st0, evEndL, 0);
    k_finish<<<1, 1, 0, st0>>>((float*)d_out);
}

// round 15
// speedup vs baseline: 1.1990x; 1.1990x over previous
#include <cuda_runtime.h>
#include <math.h>
#include <stdint.h>

#define NSCALE 2
#define NPTS   240000
#define NVOX   80000
#define NPB    120000
#define MPB    30000
#define HDIM   64
#define CDIM   20
#define MIDD   16
#define HIDD   128
#define NIMG   60000
#define NLOSS  5           // vox0, vox1, fuse0, fuse1, final
#define NB     4096        // 12-bit err quantization bins
#define QL     4095.0f
#define NCHUNK 4           // NB / 1024

// ------------------------- static device scratch -------------------------
__device__ float g_H1[NSCALE][(size_t)NVOX * HIDD];
__device__ float g_pred3d[NSCALE][(size_t)NVOX * CDIM];
__device__ int   g_counts[NSCALE][(size_t)NVOX * CDIM];
__device__ int   g_voxlab[NSCALE][NVOX];
__device__ int   g_idx[NSCALE][NIMG];
__device__ float g_P[NSCALE][(size_t)NIMG * HDIM];
__device__ float g_attw[NSCALE][(size_t)NIMG * 2];
__device__ float g_y1[NSCALE][(size_t)NIMG * HDIM];
__device__ float g_y2[NSCALE][(size_t)NIMG * HDIM];
__device__ float g_fpred[NSCALE][(size_t)NIMG * CDIM];
__device__ float g_stats[NSCALE][4 * HDIM];
__device__ unsigned long long g_hist[NLOSS][(size_t)CDIM * NB];
__device__ unsigned long long g_part[NLOSS][CDIM * NCHUNK];
__device__ double g_classLoss[NLOSS][CDIM];
__device__ int    g_gts_vox[NSCALE][CDIM];
__device__ float g_HF[(size_t)NIMG * HIDD];
__device__ float g_fpredF[(size_t)NIMG * CDIM];
__device__ float g_feats[(size_t)NIMG * 2 * HDIM];
__device__ int    g_gts_img[CDIM];
__device__ double g_loss;

// ------------------------- reduction helper -------------------------
__device__ __forceinline__ double blockReduceSumD(double v) {
    __shared__ double sh[32];
    int lane = threadIdx.x & 31, wid = threadIdx.x >> 5;
#pragma unroll
    for (int o = 16; o > 0; o >>= 1) v += __shfl_down_sync(0xffffffffu, v, o);
    if (lane == 0) sh[wid] = v;
    __syncthreads();
    int nw = (blockDim.x + 31) >> 5;
    v = (threadIdx.x < nw) ? sh[threadIdx.x] : 0.0;
    if (wid == 0) {
#pragma unroll
        for (int o = 16; o > 0; o >>= 1) v += __shfl_down_sync(0xffffffffu, v, o);
    }
    return v;
}

// ------------------------- batched elementwise kernels -------------------------
__global__ void k_scatter(const int* __restrict__ coors, const int* __restrict__ labels,
                          int* __restrict__ counts) {
    int s = blockIdx.y;
    int i = blockIdx.x * blockDim.x + threadIdx.x;
    if (i < NPTS)
        atomicAdd(&counts[(size_t)s * NVOX * CDIM +
                          (size_t)coors[(size_t)s * NPTS + i] * CDIM + labels[i]], 1);
}

__global__ void k_argmax(const int* __restrict__ counts, int* __restrict__ voxlab,
                         int* __restrict__ gts) {
    int s = blockIdx.y;
    __shared__ int h[CDIM];
    if (threadIdx.x < CDIM) h[threadIdx.x] = 0;
    __syncthreads();
    int v = blockIdx.x * blockDim.x + threadIdx.x;
    if (v < NVOX) {
        const int* row = counts + (size_t)s * NVOX * CDIM + (size_t)v * CDIM;
        int best = row[0], bi = 0;
#pragma unroll
        for (int c = 1; c < CDIM; c++) { int x = row[c]; if (x > best) { best = x; bi = c; } }
        voxlab[(size_t)s * NVOX + v] = bi;
        atomicAdd(&h[bi], 1);
    }
    __syncthreads();
    if (threadIdx.x < CDIM && h[threadIdx.x]) atomicAdd(&gts[s * CDIM + threadIdx.x], h[threadIdx.x]);
}

__global__ void k_hist(const int* __restrict__ lab, int n, int* __restrict__ gts) {
    __shared__ int h[CDIM];
    if (threadIdx.x < CDIM) h[threadIdx.x] = 0;
    __syncthreads();
    int i = blockIdx.x * blockDim.x + threadIdx.x;
    if (i < n) atomicAdd(&h[lab[i]], 1);
    __syncthreads();
    if (threadIdx.x < CDIM && h[threadIdx.x]) atomicAdd(&gts[threadIdx.x], h[threadIdx.x]);
}

__global__ void k_idxgather(const float4* __restrict__ pts4, const int* __restrict__ coors,
                            const int* __restrict__ p2img, int* __restrict__ idxArr,
                            float4* __restrict__ P4) {
    int s = blockIdx.y;
    int t = blockIdx.x * blockDim.x + threadIdx.x;
    if (t < NIMG * 16) {
        int r = t >> 4, q = t & 15;
        int b = r / MPB;
        int vi = coors[(size_t)s * NPTS + b * NPB + p2img[r]];
        if (q == 0) idxArr[(size_t)s * NIMG + r] = vi;
        P4[(size_t)s * NIMG * 16 + t] = pts4[(size_t)s * NVOX * 16 + (size_t)vi * 16 + q];
    }
}

__global__ void __launch_bounds__(256) k_attfused(
        const float* __restrict__ Pb, const float* __restrict__ imgb,
        float* __restrict__ attwb,
        const float* __restrict__ fc1w, const float* __restrict__ fc1b,
        const float* __restrict__ fc2w, const float* __restrict__ fc2b,
        const float* __restrict__ fc3w, const float* __restrict__ fc3b) {
    int s = blockIdx.y;
    __shared__ float w1[HDIM * MIDD], w2[HDIM * MIDD], w3[2 * MIDD * 2];
    __shared__ float b1[MIDD], b2[MIDD], b3[2];
    int tid = threadIdx.x;
    for (int i = tid; i < HDIM * MIDD; i += 256) {
        w1[i] = fc1w[(size_t)s * HDIM * MIDD + i];
        w2[i] = fc2w[(size_t)s * HDIM * MIDD + i];
    }
    if (tid < 2 * MIDD * 2) w3[tid] = fc3w[s * 2 * MIDD * 2 + tid];
    if (tid < MIDD) { b1[tid] = fc1b[s * MIDD + tid]; b2[tid] = fc2b[s * MIDD + tid]; }
    if (tid < 2) b3[tid] = fc3b[s * 2 + tid];
    __syncthreads();
    int r = blockIdx.x * blockDim.x + tid;
    if (r >= NIMG) return;
    float h1[MIDD], h2[MIDD];
#pragma unroll
    for (int j = 0; j < MIDD; j++) { h1[j] = b1[j]; h2[j] = b2[j]; }
    const float4* p4 = (const float4*)(Pb + (size_t)s * NIMG * HDIM + (size_t)r * HDIM);
    const float4* v4 = (const float4*)(imgb + (size_t)s * NIMG * HDIM + (size_t)r * HDIM);
#pragma unroll 4
    for (int k4 = 0; k4 < 16; k4++) {
        float4 a = p4[k4], b = v4[k4];
        const float* wa = &w1[(4 * k4) * MIDD];
        const float* wb = &w2[(4 * k4) * MIDD];
#pragma unroll
        for (int j = 0; j < MIDD; j++) {
            h1[j] += a.x * wa[j] + a.y * wa[MIDD + j] + a.z * wa[2 * MIDD + j] + a.w * wa[3 * MIDD + j];
            h2[j] += b.x * wb[j] + b.y * wb[MIDD + j] + b.z * wb[2 * MIDD + j] + b.w * wb[3 * MIDD + j];
        }
    }
    float z0 = b3[0], z1 = b3[1];
#pragma unroll
    for (int j = 0; j < MIDD; j++) {
        z0 += h1[j] * w3[j * 2 + 0] + h2[j] * w3[(MIDD + j) * 2 + 0];
        z1 += h1[j] * w3[j * 2 + 1] + h2[j] * w3[(MIDD + j) * 2 + 1];
    }
    attwb[(size_t)s * NIMG * 2 + 2 * r + 0] = 1.f / (1.f + expf(-z0));
    attwb[(size_t)s * NIMG * 2 + 2 * r + 1] = 1.f / (1.f + expf(-z1));
}

#define ROWSPB 512
__global__ void k_colstats(const float* __restrict__ y1b, const float* __restrict__ y2b,
                           float* __restrict__ statsb) {
    int s = blockIdx.y >> 1, sel = blockIdx.y & 1;
    const float* y = (sel ? y2b : y1b) + (size_t)s * NIMG * HDIM;
    float* stats = statsb + s * 4 * HDIM + sel * 2 * HDIM;
    const int col = threadIdx.x & 63;
    const int grp = threadIdx.x >> 6;
    float sv = 0.f, q = 0.f;
    int r0 = blockIdx.x * ROWSPB;
    int rend = r0 + ROWSPB; if (rend > NIMG) rend = NIMG;
    for (int r = r0 + grp; r < rend; r += 4) {
        float v = y[(size_t)r * HDIM + col];
        sv += v; q += v * v;
    }
    __shared__ float sh[2][4][64];
    sh[0][grp][col] = sv; sh[1][grp][col] = q;
    __syncthreads();
    if (grp == 0) {
        sv = sh[0][0][col] + sh[0][1][col] + sh[0][2][col] + sh[0][3][col];
        q = sh[1][0][col] + sh[1][1][col] + sh[1][2][col] + sh[1][3][col];
        atomicAdd(&stats[col], sv);
        atomicAdd(&stats[64 + col], q);
    }
}

__global__ void k_fuse(const float* __restrict__ y1b, const float* __restrict__ y2b,
                       const float* __restrict__ attwb, const float* __restrict__ statsb,
                       const float* __restrict__ g1, const float* __restrict__ b1,
                       const float* __restrict__ g2, const float* __restrict__ b2) {
    int s = blockIdx.y;
    int t = blockIdx.x * blockDim.x + threadIdx.x;
    if (t >= NIMG * HDIM) return;
    int r = t >> 6, c = t & 63;
    const float* stats = statsb + s * 4 * HDIM;
    const float n = (float)NIMG;
    float mu1 = stats[c] / n;        float var1 = stats[64 + c] / n - mu1 * mu1;
    float mu2 = stats[128 + c] / n;  float var2 = stats[192 + c] / n - mu2 * mu2;
    float v1 = fmaxf((y1b[(size_t)s * NIMG * HDIM + t] - mu1) * rsqrtf(var1 + 1e-5f) * g1[s * HDIM + c] + b1[s * HDIM + c], 0.f);
    float v2 = fmaxf((y2b[(size_t)s * NIMG * HDIM + t] - mu2) * rsqrtf(var2 + 1e-5f) * g2[s * HDIM + c] + b2[s * HDIM + c], 0.f);
    g_feats[(size_t)r * (2 * HDIM) + s * HDIM + c] =
        v1 * attwb[(size_t)s * NIMG * 2 + 2 * r] + v2 * attwb[(size_t)s * NIMG * 2 + 2 * r + 1];
}

// ------------------------- big GEMM (f32x2), batched via blockIdx.z -------------------------
template <int BM, int BN, int TM, int TN, bool RELU>
__global__ void __launch_bounds__(256) k_gemm2(const float* __restrict__ A0, int lda, size_t sA,
                                               const float* __restrict__ W0, size_t sW,
                                               const float* __restrict__ bias0, size_t sB,
                                               float* __restrict__ C0, size_t sC,
                                               int M, int N, int K) {
    constexpr int TX = BN / TN;
    constexpr int TY = BM / TM;
    static_assert(TX * TY == 256 && TM == 8 && (TN == 4 || TN == 8), "bad tile");
    const float* A = A0 + (size_t)blockIdx.z * sA;
    const float* W = W0 + (size_t)blockIdx.z * sW;
    const float* bias = bias0 + (size_t)blockIdx.z * sB;
    float* Cm = C0 + (size_t)blockIdx.z * sC;
    __shared__ __align__(16) float As[16][BM + 4];
    __shared__ __align__(16) float Ws[16][BN + 4];
    const int bm = blockIdx.y * BM, bn = blockIdx.x * BN;
    const int tid = threadIdx.x;
    const int tx = tid % TX, ty = tid / TX;
    unsigned long long acc[TM][TN / 2] = {};
    for (int k0 = 0; k0 < K; k0 += 16) {
#pragma unroll
        for (int it = 0; it < BM / 64; it++) {
            int g = tid + it * 256;
            int m = g >> 2, q = g & 3;
            int gm = bm + m;
            float4 v = make_float4(0.f, 0.f, 0.f, 0.f);
            if (gm < M) v = *(const float4*)&A[(size_t)gm * lda + k0 + 4 * q];
            As[4 * q + 0][m] = v.x; As[4 * q + 1][m] = v.y;
            As[4 * q + 2][m] = v.z; As[4 * q + 3][m] = v.w;
        }
#pragma unroll
        for (int it = 0; it < BN / 64; it++) {
            int g = tid + it * 256;
            int kk = g / (BN / 4), nq = g % (BN / 4);
            *(float4*)&Ws[kk][4 * nq] = *(const float4*)&W[(size_t)(k0 + kk) * N + bn + 4 * nq];
        }
        __syncthreads();
#pragma unroll
        for (int kk = 0; kk < 16; kk++) {
            float a[TM];
            *(float4*)&a[0] = *(const float4*)&As[kk][ty * TM];
            *(float4*)&a[4] = *(const float4*)&As[kk][ty * TM + 4];
            unsigned long long b2[TN / 2];
            *(ulonglong2*)&b2[0] = *(const ulonglong2*)&Ws[kk][tx * TN];
            if constexpr (TN == 8) {
                *(ulonglong2*)&b2[2] = *(const ulonglong2*)&Ws[kk][tx * TN + 4];
            }
#pragma unroll
            for (int i = 0; i < TM; i++) {
                unsigned long long a2;
                asm("mov.b64 %0, {%1, %1};" : "=l"(a2) : "f"(a[i]));
#pragma unroll
                for (int j = 0; j < TN / 2; j++)
                    asm("fma.rn.f32x2 %0, %1, %2, %0;" : "+l"(acc[i][j]) : "l"(a2), "l"(b2[j]));
            }
        }
        __syncthreads();
    }
#pragma unroll
    for (int i = 0; i < TM; i++) {
        int gm = bm + ty * TM + i;
        if (gm >= M) continue;
#pragma unroll
        for (int j = 0; j < TN / 2; j++) {
            int gn = bn + tx * TN + 2 * j;
            float lo = __uint_as_float((unsigned)(acc[i][j] & 0xFFFFFFFFull)) + bias[gn];
            float hi = __uint_as_float((unsigned)(acc[i][j] >> 32)) + bias[gn + 1];
            if (RELU) { lo = fmaxf(lo, 0.f); hi = fmaxf(hi, 0.f); }
            *(float2*)&Cm[(size_t)gm * N + gn] = make_float2(lo, hi);
        }
    }
}

// ------------------------- small-N GEMM (f32x2, N padded to 32) -------------------------
template <bool RELU>
__global__ void __launch_bounds__(256) k_gemmS(const float* __restrict__ A0, int lda, size_t sA,
                                               const float* __restrict__ W0, size_t sW,
                                               const float* __restrict__ bias0, size_t sB,
                                               float* __restrict__ C0, size_t sC,
                                               int M, int N, int K) {
    constexpr int BM = 256, BN = 32, TM = 8, TN = 4;
    constexpr int TX = BN / TN;   // 8
    const float* A = A0 + (size_t)blockIdx.z * sA;
    const float* W = W0 + (size_t)blockIdx.z * sW;
    const float* bias = bias0 + (size_t)blockIdx.z * sB;
    float* Cm = C0 + (size_t)blockIdx.z * sC;
    __shared__ __align__(16) float As[16][BM + 4];
    __shared__ __align__(16) float Ws[16][BN + 4];
    const int bm = blockIdx.y * BM;
    const int tid = threadIdx.x;
    const int tx = tid % TX, ty = tid / TX;   // ty in 0..31
    unsigned long long acc[TM][TN / 2] = {};
    for (int k0 = 0; k0 < K; k0 += 16) {
#pragma unroll
        for (int it = 0; it < BM / 64; it++) {
            int g = tid + it * 256;
            int m = g >> 2, q = g & 3;
            int gm = bm + m;
            float4 v = make_float4(0.f, 0.f, 0.f, 0.f);
            if (gm < M) v = *(const float4*)&A[(size_t)gm * lda + k0 + 4 * q];
            As[4 * q + 0][m] = v.x; As[4 * q + 1][m] = v.y;
            As[4 * q + 2][m] = v.z; As[4 * q + 3][m] = v.w;
        }
#pragma unroll
        for (int e = tid; e < 16 * BN; e += 256) {
            int kk = e >> 5, n2 = e & 31;
            Ws[kk][n2] = (n2 < N) ? W[(size_t)(k0 + kk) * N + n2] : 0.f;
        }
        __syncthreads();
#pragma unroll
        for (int kk = 0; kk < 16; kk++) {
            float a[TM];
            *(float4*)&a[0] = *(const float4*)&As[kk][ty * TM];
            *(float4*)&a[4] = *(const float4*)&As[kk][ty * TM + 4];
            unsigned long long b2[TN / 2];
            *(ulonglong2*)&b2[0] = *(const ulonglong2*)&Ws[kk][tx * TN];
#pragma unroll
            for (int i = 0; i < TM; i++) {
                unsigned long long a2;
                asm("mov.b64 %0, {%1, %1};" : "=l"(a2) : "f"(a[i]));
#pragma unroll
                for (int j = 0; j < TN / 2; j++)
                    asm("fma.rn.f32x2 %0, %1, %2, %0;" : "+l"(acc[i][j]) : "l"(a2), "l"(b2[j]));
            }
        }
        __syncthreads();
    }
#pragma unroll
    for (int i = 0; i < TM; i++) {
        int gm = bm + ty * TM + i;
        if (gm >= M) continue;
#pragma unroll
        for (int j = 0; j < TN / 2; j++) {
            int gn = tx * TN + 2 * j;
            if (gn + 1 < N) {
                float lo = __uint_as_float((unsigned)(acc[i][j] & 0xFFFFFFFFull)) + bias[gn];
                float hi = __uint_as_float((unsigned)(acc[i][j] >> 32)) + bias[gn + 1];
                if (RELU) { lo = fmaxf(lo, 0.f); hi = fmaxf(hi, 0.f); }
                *(float2*)&Cm[(size_t)gm * N + gn] = make_float2(lo, hi);
            } else if (gn < N) {
                float lo = __uint_as_float((unsigned)(acc[i][j] & 0xFFFFFFFFull)) + bias[gn];
                if (RELU) lo = fmaxf(lo, 0.f);
                Cm[(size_t)gm * N + gn] = lo;
            }
        }
    }
}

// ------------------------- loss kernels -------------------------
__global__ void k_softmax_hist(const float* __restrict__ logits0, size_t sL,
                               const int* __restrict__ lab0, int sLab,
                               int n, float ce_w, unsigned long long* __restrict__ hist0) {
    int s = blockIdx.y;
    const float* logits = logits0 + (size_t)s * sL;
    const int* lab = lab0 + (size_t)s * sLab;
    unsigned long long* hist = hist0 + (size_t)s * CDIM * NB;
    int i = blockIdx.x * blockDim.x + threadIdx.x;
    double ce = 0.0;
    if (i < n) {
        float z[CDIM];
        const float4* zr = (const float4*)(logits + (size_t)i * CDIM);
#pragma unroll
        for (int q4 = 0; q4 < 5; q4++) {
            float4 v = zr[q4];
            z[4 * q4 + 0] = v.x; z[4 * q4 + 1] = v.y;
            z[4 * q4 + 2] = v.z; z[4 * q4 + 3] = v.w;
        }
        float m = z[0];
#pragma unroll
        for (int c = 1; c < CDIM; c++) m = fmaxf(m, z[c]);
        float se = 0.f;
#pragma unroll
        for (int c = 0; c < CDIM; c++) se += expf(z[c] - m);
        float ls = logf(se);
        int l = lab[i];
        ce = -(double)(z[l] - m - ls);
#pragma unroll
        for (int c = 0; c < CDIM; c++) {
            float p = expf(z[c] - m - ls);
            unsigned long long fg = (c == l) ? 1ull : 0ull;
            float err = fabsf((float)(c == l) - p);
            uint32_t q = (uint32_t)__float2uint_rn(err * QL);
            if (q > (NB - 1)) q = NB - 1;
            atomicAdd(&hist[(size_t)c * NB + q], (1ull << 32) | fg);
        }
    }
    double tot = blockReduceSumD(ce);
    if (threadIdx.x == 0) atomicAdd(&g_loss, tot * (double)ce_w / (double)n);
}

__global__ void k_lovpart(const unsigned long long* __restrict__ hist0,
                          unsigned long long* __restrict__ part0) {
    int inst = blockIdx.x / (CDIM * NCHUNK);
    int rem = blockIdx.x % (CDIM * NCHUNK);
    int c = rem / NCHUNK, chunk = rem % NCHUNK;
    const unsigned long long* h = hist0 + (size_t)inst * CDIM * NB + (size_t)c * NB + chunk * 1024;
    int t = threadIdx.x;
    unsigned long long s = 0;
#pragma unroll
    for (int i = 0; i < 4; i++) s += h[t * 4 + i];
    __shared__ unsigned long long sh[8];
#pragma unroll
    for (int o = 16; o > 0; o >>= 1) s += __shfl_down_sync(0xffffffffu, s, o);
    if ((t & 31) == 0) sh[t >> 5] = s;
    __syncthreads();
    if (t == 0) {
        unsigned long long v = 0;
#pragma unroll
        for (int w = 0; w < 8; w++) v += sh[w];
        part0[inst * CDIM * NCHUNK + rem] = v;
    }
}

__global__ void k_loveval(const unsigned long long* __restrict__ hist0,
                          const unsigned long long* __restrict__ part0,
                          const int* __restrict__ gts0, int sGts,
                          double* __restrict__ cls0) {
    int inst = blockIdx.x / (CDIM * NCHUNK);
    int rem = blockIdx.x % (CDIM * NCHUNK);
    int c = rem / NCHUNK, chunk = rem % NCHUNK;
    const int* gts = gts0 + inst * sGts;
    int gi = gts[c];
    if (gi == 0) return;
    float g = (float)gi;
    int t = threadIdx.x;
    __shared__ unsigned long long shOff;
    __shared__ unsigned long long shWarp[8];
    __shared__ double shD[8];
    const unsigned long long* part = part0 + inst * CDIM * NCHUNK;
    if (t == 0) {
        unsigned long long o = 0;
        for (int k = chunk + 1; k < NCHUNK; k++) o += part[c * NCHUNK + k];
        shOff = o;
    }
    const unsigned long long* h = hist0 + (size_t)inst * CDIM * NB + (size_t)c * NB + chunk * 1024;
    unsigned long long v[4]; unsigned long long tot = 0;
#pragma unroll
    for (int i = 0; i < 4; i++) { v[i] = h[1023 - (4 * t + i)]; tot += v[i]; }
    unsigned long long incl = tot;
#pragma unroll
    for (int o = 1; o < 32; o <<= 1) {
        unsigned long long u = __shfl_up_sync(0xffffffffu, incl, o);
        if ((t & 31) >= o) incl += u;
    }
    if ((t & 31) == 31) shWarp[t >> 5] = incl;
    __syncthreads();
    unsigned long long warpOff = 0;
    for (int w = 0; w < (t >> 5); w++) warpOff += shWarp[w];
    unsigned long long excl = shOff + warpOff + (incl - tot);
    unsigned long long P = excl >> 32, F = excl & 0xFFFFFFFFull;
    double acc = 0.0;
#pragma unroll
    for (int i = 0; i < 4; i++) {
        unsigned long long nb = v[i] >> 32, fb = v[i] & 0xFFFFFFFFull;
        if (nb) {
            int bin = chunk * 1024 + 1023 - (4 * t + i);
            float e = (float)bin * (1.0f / QL);
            float Pf = (float)P, Ff = (float)F;
            float Js = 1.f - (g - Ff) / (g + Pf - Ff);
            float Pe = (float)(P + nb), Fe = (float)(F + fb);
            float Je = 1.f - (g - Fe) / (g + Pe - Fe);
            acc += (double)(e * (Je - Js));
            P += nb; F += fb;
        }
    }
#pragma unroll
    for (int o = 16; o > 0; o >>= 1) acc += __shfl_down_sync(0xffffffffu, acc, o);
    if ((t & 31) == 0) shD[t >> 5] = acc;
    __syncthreads();
    if (t == 0) {
        double s = 0.0;
#pragma unroll
        for (int w = 0; w < 8; w++) s += shD[w];
        atomicAdd(&cls0[inst * CDIM + c], s);
    }
}

__global__ void k_lovreduceAll() {
    int tid = threadIdx.x;
    const float w[NLOSS] = {1.f, 1.f, 0.5f, 0.5f, 1.f};
    double total = 0.0;
#pragma unroll
    for (int li = 0; li < NLOSS; li++) {
        const int* gts = (li == 0) ? g_gts_vox[0] : (li == 1) ? g_gts_vox[1] : g_gts_img;
        double v = 0.0; int pc = 0;
        if (tid < CDIM && gts[tid] > 0) { v = g_classLoss[li][tid]; pc = 1; }
#pragma unroll
        for (int o = 16; o > 0; o >>= 1) {
            v += __shfl_down_sync(0xffffffffu, v, o);
            pc += __shfl_down_sync(0xffffffffu, pc, o);
        }
        if (tid == 0) total += (double)w[li] * v / (double)(pc > 0 ? pc : 1);
    }
    if (tid == 0) atomicAdd(&g_loss, total);
}

__global__ void k_kl(double w, const float* __restrict__ fpredb,
                     const float* __restrict__ predb, const int* __restrict__ idxb) {
    int s = blockIdx.y;
    int r = blockIdx.x * blockDim.x + threadIdx.x;
    double local = 0.0;
    if (r < NIMG) {
        float zf[CDIM], zp[CDIM];
        int vi = idxb[(size_t)s * NIMG + r];
        const float4* fr = (const float4*)(fpredb + (size_t)s * NIMG * CDIM + (size_t)r * CDIM);
        const float4* pr = (const float4*)(predb + (size_t)s * NVOX * CDIM + (size_t)vi * CDIM);
#pragma unroll
        for (int q4 = 0; q4 < 5; q4++) {
            float4 a = fr[q4], b = pr[q4];
            zf[4 * q4 + 0] = a.x; zf[4 * q4 + 1] = a.y; zf[4 * q4 + 2] = a.z; zf[4 * q4 + 3] = a.w;
            zp[4 * q4 + 0] = b.x; zp[4 * q4 + 1] = b.y; zp[4 * q4 + 2] = b.z; zp[4 * q4 + 3] = b.w;
        }
        float mf = zf[0], mp = zp[0];
#pragma unroll
        for (int c = 1; c < CDIM; c++) { mf = fmaxf(mf, zf[c]); mp = fmaxf(mp, zp[c]); }
        float sf = 0.f, sp = 0.f;
#pragma unroll
        for (int c = 0; c < CDIM; c++) { sf += expf(zf[c] - mf); sp += expf(zp[c] - mp); }
        float lsf = logf(sf), lsp = logf(sp);
        float acc = 0.f;
#pragma unroll
        for (int c = 0; c < CDIM; c++) {
            float lp = zf[c] - mf - lsf;
            float p = expf(lp);
            float lq = zp[c] - mp - lsp;
            acc += p * (lp - lq);
        }
        local = (double)acc;
    }
    double tot = blockReduceSumD(local);
    if (threadIdx.x == 0) atomicAdd(&g_loss, tot * w);
}

__global__ void k_finish(float* out) { out[0] = (float)g_loss; }

// ------------------------- host -------------------------
static inline int ceildiv(int a, int b) { return (a + b - 1) / b; }

extern "C" void kernel_launch(void* const* d_in, const int* in_sizes, int n_in,
                              void* d_out, int out_size) {
    const float* img_feat = (const float*)d_in[0];
    const float* pts_feat = (const float*)d_in[1];
    const int*   coors_inv = (const int*)d_in[2];
    const int*   labels   = (const int*)d_in[3];
    const int*   img_label = (const int*)d_in[4];
    const int*   p2img    = (const int*)d_in[5];
    const float* w3a = (const float*)d_in[6];  const float* b3a = (const float*)d_in[7];
    const float* w3b = (const float*)d_in[8];  const float* b3b = (const float*)d_in[9];
    const float* wfa = (const float*)d_in[10]; const float* bfa = (const float*)d_in[11];
    const float* wfb = (const float*)d_in[12]; const float* bfb = (const float*)d_in[13];
    const float* fc1w = (const float*)d_in[14]; const float* fc1b = (const float*)d_in[15];
    const float* fc2w = (const float*)d_in[16]; const float* fc2b = (const float*)d_in[17];
    const float* fc3w = (const float*)d_in[18]; const float* fc3b = (const float*)d_in[19];
    const float* c1w = (const float*)d_in[20]; const float* c1b = (const float*)d_in[21];
    const float* bn1g = (const float*)d_in[22]; const float* bn1b = (const float*)d_in[23];
    const float* c2w = (const float*)d_in[24]; const float* c2b = (const float*)d_in[25];
    const float* bn2g = (const float*)d_in[26]; const float* bn2b = (const float*)d_in[27];
    const float* clw1 = (const float*)d_in[28]; const float* clb1 = (const float*)d_in[29];
    const float* clw2 = (const float*)d_in[30]; const float* clb2 = (const float*)d_in[31];

    void *pv;
    cudaGetSymbolAddress(&pv, g_H1);       float* H1b = (float*)pv;
    cudaGetSymbolAddress(&pv, g_pred3d);   float* predb = (float*)pv;
    cudaGetSymbolAddress(&pv, g_counts);   int* countsb = (int*)pv;
    cudaGetSymbolAddress(&pv, g_voxlab);   int* voxlabb = (int*)pv;
    cudaGetSymbolAddress(&pv, g_idx);      int* idxb = (int*)pv;
    cudaGetSymbolAddress(&pv, g_P);        float* Pb = (float*)pv;
    cudaGetSymbolAddress(&pv, g_attw);     float* attwb = (float*)pv;
    cudaGetSymbolAddress(&pv, g_y1);       float* y1b = (float*)pv;
    cudaGetSymbolAddress(&pv, g_y2);       float* y2b = (float*)pv;
    cudaGetSymbolAddress(&pv, g_fpred);    float* fpredb = (float*)pv;
    cudaGetSymbolAddress(&pv, g_stats);    float* statsb = (float*)pv;
    cudaGetSymbolAddress(&pv, g_hist);     unsigned long long* histb = (unsigned long long*)pv;
    cudaGetSymbolAddress(&pv, g_part);     unsigned long long* partb = (unsigned long long*)pv;
    cudaGetSymbolAddress(&pv, g_classLoss);double* clsb = (double*)pv;
    cudaGetSymbolAddress(&pv, g_gts_vox);  int* gtsvoxb = (int*)pv;
    cudaGetSymbolAddress(&pv, g_HF);       float* HF = (float*)pv;
    cudaGetSymbolAddress(&pv, g_fpredF);   float* fpredF = (float*)pv;
    cudaGetSymbolAddress(&pv, g_feats);    float* feats = (float*)pv;
    cudaGetSymbolAddress(&pv, g_gts_img);  int* gtsimg = (int*)pv;
    cudaGetSymbolAddress(&pv, g_loss);     void* p_loss = pv;

    static cudaStream_t sM = nullptr, sL = nullptr;
    static cudaEvent_t evFork = nullptr, evPred = nullptr, evFpred = nullptr;
    static cudaEvent_t evFeats = nullptr, evY2 = nullptr;
    static cudaEvent_t evEndM = nullptr, evEndL = nullptr;
    if (!sM) {
        cudaStreamCreateWithFlags(&sM, cudaStreamNonBlocking);
        cudaStreamCreateWithFlags(&sL, cudaStreamNonBlocking);
        cudaEventCreateWithFlags(&evFork, cudaEventDisableTiming);
        cudaEventCreateWithFlags(&evPred, cudaEventDisableTiming);
        cudaEventCreateWithFlags(&evFpred, cudaEventDisableTiming);
        cudaEventCreateWithFlags(&evFeats, cudaEventDisableTiming);
        cudaEventCreateWithFlags(&evY2, cudaEventDisableTiming);
        cudaEventCreateWithFlags(&evEndM, cudaEventDisableTiming);
        cudaEventCreateWithFlags(&evEndL, cudaEventDisableTiming);
    }

    cudaStream_t st0 = 0;
    cudaMemsetAsync(p_loss, 0, sizeof(double), st0);
    cudaMemsetAsync(gtsimg, 0, CDIM * sizeof(int), st0);
    cudaMemsetAsync(countsb, 0, (size_t)NSCALE * NVOX * CDIM * sizeof(int), st0);
    cudaMemsetAsync(gtsvoxb, 0, NSCALE * CDIM * sizeof(int), st0);
    cudaMemsetAsync(histb, 0, (size_t)NLOSS * CDIM * NB * sizeof(unsigned long long), st0);
    cudaMemsetAsync(clsb, 0, NLOSS * CDIM * sizeof(double), st0);
    cudaMemsetAsync(statsb, 0, NSCALE * 4 * HDIM * sizeof(float), st0);
    k_hist<<<ceildiv(NIMG, 256), 256, 0, st0>>>(img_label, NIMG, gtsimg);
    cudaEventRecord(evFork, st0);
    cudaStreamWaitEvent(sM, evFork, 0);
    cudaStreamWaitEvent(sL, evFork, 0);

    auto hist = [&](int i) { return histb + (size_t)i * CDIM * NB; };
    auto part = [&](int i) { return partb + (size_t)i * CDIM * NCHUNK; };
    auto cls  = [&](int i) { return clsb + (size_t)i * CDIM; };

    // ===== LOSS stream independent prefix (record evY2 before sM waits) =====
    k_gemm2<128, 64, 8, 4, false><<<dim3(1, ceildiv(NIMG, 128), 2), 256, 0, sL>>>(
        img_feat, HDIM, (size_t)NIMG * HDIM, c2w, (size_t)HDIM * HDIM, c2b, HDIM,
        y2b, (size_t)NIMG * HDIM, NIMG, HDIM, HDIM);
    cudaEventRecord(evY2, sL);
    k_scatter<<<dim3(ceildiv(NPTS, 256), 2), 256, 0, sL>>>(coors_inv, labels, countsb);
    k_argmax<<<dim3(ceildiv(NVOX, 256), 2), 256, 0, sL>>>(countsb, voxlabb, gtsvoxb);

    // ================= MAIN stream =================
    k_gemm2<128, 128, 8, 8, true><<<dim3(1, ceildiv(NVOX, 128), 2), 256, 0, sM>>>(
        pts_feat, HDIM, (size_t)NVOX * HDIM, w3a, (size_t)HDIM * HIDD, b3a, HIDD,
        H1b, (size_t)NVOX * HIDD, NVOX, HIDD, HDIM);
    k_gemmS<false><<<dim3(1, ceildiv(NVOX, 256), 2), 256, 0, sM>>>(
        H1b, HIDD, (size_t)NVOX * HIDD, w3b, (size_t)HIDD * CDIM, b3b, CDIM,
        predb, (size_t)NVOX * CDIM, NVOX, CDIM, HIDD);
    cudaEventRecord(evPred, sM);

    k_idxgather<<<dim3(ceildiv(NIMG * 16, 256), 2), 256, 0, sM>>>(
        (const float4*)pts_feat, coors_inv, p2img, idxb, (float4*)Pb);
    k_attfused<<<dim3(ceildiv(NIMG, 256), 2), 256, 0, sM>>>(
        Pb, img_feat, attwb, fc1w, fc1b, fc2w, fc2b, fc3w, fc3b);
    k_gemm2<128, 64, 8, 4, false><<<dim3(1, ceildiv(NIMG, 128), 2), 256, 0, sM>>>(
        Pb, HDIM, (size_t)NIMG * HDIM, c1w, (size_t)HDIM * HDIM, c1b, HDIM,
        y1b, (size_t)NIMG * HDIM, NIMG, HDIM, HDIM);
    cudaStreamWaitEvent(sM, evY2, 0);
    k_colstats<<<dim3(ceildiv(NIMG, ROWSPB), 4), 256, 0, sM>>>(y1b, y2b, statsb);
    k_fuse<<<dim3(ceildiv(NIMG * HDIM, 256), 2), 256, 0, sM>>>(
        y1b, y2b, attwb, statsb, bn1g, bn1b, bn2g, bn2b);
    cudaEventRecord(evFeats, sM);

    k_gemm2<128, 128, 8, 8, true><<<dim3(1, ceildiv(NIMG, 128), 2), 256, 0, sM>>>(
        feats, 2 * HDIM, (size_t)HDIM, wfa, (size_t)HDIM * HIDD, bfa, HIDD,
        H1b, (size_t)NVOX * HIDD, NIMG, HIDD, HDIM);
    k_gemmS<false><<<dim3(1, ceildiv(NIMG, 256), 2), 256, 0, sM>>>(
        H1b, HIDD, (size_t)NVOX * HIDD, wfb, (size_t)HIDD * CDIM, bfb, CDIM,
        fpredb, (size_t)NIMG * CDIM, NIMG, CDIM, HIDD);
    cudaEventRecord(evFpred, sM);
    cudaEventRecord(evEndM, sM);

    // ===== LOSS stream gated suffix =====
    cudaStreamWaitEvent(sL, evPred, 0);
    k_softmax_hist<<<dim3(ceildiv(NVOX, 512), 2), 512, 0, sL>>>(
        predb, (size_t)NVOX * CDIM, voxlabb, NVOX, NVOX, 1.0f, hist(0));
    k_lovpart<<<2 * CDIM * NCHUNK, 256, 0, sL>>>(hist(0), part(0));
    k_loveval<<<2 * CDIM * NCHUNK, 256, 0, sL>>>(hist(0), part(0), gtsvoxb, CDIM, cls(0));

    cudaStreamWaitEvent(sL, evFeats, 0);
    k_gemm2<128, 128, 8, 8, true><<<dim3(1, ceildiv(NIMG, 128), 1), 256, 0, sL>>>(
        feats, 2 * HDIM, 0, clw1, 0, clb1, 0, HF, 0, NIMG, HIDD, 2 * HDIM);
    k_gemmS<false><<<dim3(1, ceildiv(NIMG, 256), 1), 256, 0, sL>>>(
        HF, HIDD, 0, clw2, 0, clb2, 0, fpredF, 0, NIMG, CDIM, HIDD);
    k_softmax_hist<<<dim3(ceildiv(NIMG, 512), 1), 512, 0, sL>>>(
        fpredF, 0, img_label, 0, NIMG, 1.0f, hist(4));
    k_lovpart<<<CDIM * NCHUNK, 256, 0, sL>>>(hist(4), part(4));
    k_loveval<<<CDIM * NCHUNK, 256, 0, sL>>>(hist(4), part(4), gtsimg, 0, cls(4));

    cudaStreamWaitEvent(sL, evFpred, 0);
    k_softmax_hist<<<dim3(ceildiv(NIMG, 512), 2), 512, 0, sL>>>(
        fpredb, (size_t)NIMG * CDIM, img_label, 0, NIMG, 0.5f, hist(2));
    k_lovpart<<<2 * CDIM * NCHUNK, 256, 0, sL>>>(hist(2), part(2));
    k_loveval<<<2 * CDIM * NCHUNK, 256, 0, sL>>>(hist(2), part(2), gtsimg, 0, cls(2));
    k_kl<<<dim3(ceildiv(NIMG, 256), 2), 256, 0, sL>>>(
        0.025 / ((double)NIMG * (double)CDIM), fpredb, predb, idxb);
    k_lovreduceAll<<<1, 32, 0, sL>>>();
    cudaEventRecord(evEndL, sL);

    cudaStreamWaitEvent(st0, evEndM, 0);
    cudaStreamWaitEvent(st0, evEndL, 0);
    k_finish<<<1, 1, 0, st0>>>((float*)d_out);
}